// round 9
// baseline (speedup 1.0000x reference)
#include <cuda_runtime.h>

typedef unsigned long long u64;

// ---- packed f32x2 helpers (sm_103a) ----
__device__ __forceinline__ u64 pack2(float lo, float hi) {
    u64 r; asm("mov.b64 %0, {%1, %2};" : "=l"(r) : "f"(lo), "f"(hi)); return r;
}
__device__ __forceinline__ void unpack2(u64 v, float& lo, float& hi) {
    asm("mov.b64 {%0, %1}, %2;" : "=f"(lo), "=f"(hi) : "l"(v));  // reg-pair rename: free in SASS
}
__device__ __forceinline__ u64 fma2(u64 a, u64 b, u64 c) {
    u64 d; asm("fma.rn.f32x2 %0, %1, %2, %3;" : "=l"(d) : "l"(a), "l"(b), "l"(c));
    return d;
}

#define TPB 256
#define PPT 4
#define MAX_PAIRS 512

// Fixed-point accumulator: integer atomics commute exactly -> deterministic.
#define SUM_SCALE 4294967296.0 // 2^32

__device__ unsigned long long g_sum = 0ULL;
__device__ unsigned int g_count = 0u;

// Palette as PAIRS packed in f32x2 lanes:
//   s_xy[k] = { (px_2k,px_2k+1), (py_2k,py_2k+1) }
//   s_zc[k] = { (pz_2k,pz_2k+1), (c_2k,c_2k+1) },  c = 0.5*|p|^2
// Per point: splat (-x,-x),(-y,-y),(-z,-z); per pair: 3 fma2 -> 2 scores;
// min via 2 FMNMX on the (free) unpacked halves.
// d = sqrt(max(|x|^2 + 2*min_score, 0)).

__global__ void __launch_bounds__(TPB, 1)
ncd_fused(const float* __restrict__ pts, const float* __restrict__ pal,
          float* __restrict__ out, int N, int M)
{
    __shared__ ulonglong2 s_xy[MAX_PAIRS];
    __shared__ ulonglong2 s_zc[MAX_PAIRS];
    __shared__ float s_warp[TPB / 32];
    __shared__ bool s_last;

    const int tid = threadIdx.x;
    const int npair = (M + 1) >> 1;
    const long long base = ((long long)blockIdx.x * TPB + tid) * PPT;
    const bool fast = (base + PPT <= (long long)N) && (M == 128);

    // ---- issue point loads FIRST: their latency hides under palette build
    float x0=0.f,y0=0.f,z0=0.f,x1=0.f,y1=0.f,z1=0.f;
    float x2=0.f,y2=0.f,z2=0.f,x3=0.f,y3=0.f,z3=0.f;
    if (fast) {
        const float4* p4 = (const float4*)(pts + base * 3);
        const float4 f0 = p4[0], f1 = p4[1], f2 = p4[2];
        x0 = f0.x; y0 = f0.y; z0 = f0.z;
        x1 = f0.w; y1 = f1.x; z1 = f1.y;
        x2 = f1.z; y2 = f1.w; z2 = f2.x;
        x3 = f2.y; y3 = f2.z; z3 = f2.w;
    }

    // ---- palette build: one pair per thread (no loop; 64 threads for M=128)
    if (tid < npair) {
        const int k = tid;
        const int j0 = 2 * k;
        const int j1 = (2 * k + 1 < M) ? (2 * k + 1) : j0;
        const float px0 = pal[3 * j0 + 0], py0 = pal[3 * j0 + 1], pz0 = pal[3 * j0 + 2];
        const float px1 = pal[3 * j1 + 0], py1 = pal[3 * j1 + 1], pz1 = pal[3 * j1 + 2];
        const float c0 = 0.5f * (px0 * px0 + py0 * py0 + pz0 * pz0);
        const float c1 = 0.5f * (px1 * px1 + py1 * py1 + pz1 * pz1);
        s_xy[k] = make_ulonglong2(pack2(px0, px1), pack2(py0, py1));
        s_zc[k] = make_ulonglong2(pack2(pz0, pz1), pack2(c0, c1));
    } else if (npair > TPB) {   // generic M fallback (not taken for M=128)
        for (int k = tid; k < npair; k += TPB) {
            const int j0 = 2 * k;
            const int j1 = (2 * k + 1 < M) ? (2 * k + 1) : j0;
            const float px0 = pal[3 * j0 + 0], py0 = pal[3 * j0 + 1], pz0 = pal[3 * j0 + 2];
            const float px1 = pal[3 * j1 + 0], py1 = pal[3 * j1 + 1], pz1 = pal[3 * j1 + 2];
            const float c0 = 0.5f * (px0 * px0 + py0 * py0 + pz0 * pz0);
            const float c1 = 0.5f * (px1 * px1 + py1 * py1 + pz1 * pz1);
            s_xy[k] = make_ulonglong2(pack2(px0, px1), pack2(py0, py1));
            s_zc[k] = make_ulonglong2(pack2(pz0, pz1), pack2(c0, c1));
        }
    }
    __syncthreads();

    float tsum = 0.0f;

    if (fast) {
        const u64 sx0 = pack2(-x0, -x0), sy0 = pack2(-y0, -y0), sz0 = pack2(-z0, -z0);
        const u64 sx1 = pack2(-x1, -x1), sy1 = pack2(-y1, -y1), sz1 = pack2(-z1, -z1);
        const u64 sx2 = pack2(-x2, -x2), sy2 = pack2(-y2, -y2), sz2 = pack2(-z2, -z2);
        const u64 sx3 = pack2(-x3, -x3), sy3 = pack2(-y3, -y3), sz3 = pack2(-z3, -z3);
        const float n0 = __fmaf_rn(x0, x0, __fmaf_rn(y0, y0, z0 * z0));
        const float n1 = __fmaf_rn(x1, x1, __fmaf_rn(y1, y1, z1 * z1));
        const float n2 = __fmaf_rn(x2, x2, __fmaf_rn(y2, y2, z2 * z2));
        const float n3 = __fmaf_rn(x3, x3, __fmaf_rn(y3, y3, z3 * z3));

        // Init accumulators from pair 0 (no 1e30 seeds).
        float m0l, m0h, m1l, m1h, m2l, m2h, m3l, m3h;
        {
            const ulonglong2 a = s_xy[0];
            const ulonglong2 b = s_zc[0];
            unpack2(fma2(sx0, a.x, fma2(sy0, a.y, fma2(sz0, b.x, b.y))), m0l, m0h);
            unpack2(fma2(sx1, a.x, fma2(sy1, a.y, fma2(sz1, b.x, b.y))), m1l, m1h);
            unpack2(fma2(sx2, a.x, fma2(sy2, a.y, fma2(sz2, b.x, b.y))), m2l, m2h);
            unpack2(fma2(sx3, a.x, fma2(sy3, a.y, fma2(sz3, b.x, b.y))), m3l, m3h);
        }

        #pragma unroll
        for (int k = 1; k < 64; k++) {
            const ulonglong2 a = s_xy[k];
            const ulonglong2 b = s_zc[k];
            const u64 t0 = fma2(sx0, a.x, fma2(sy0, a.y, fma2(sz0, b.x, b.y)));
            const u64 t1 = fma2(sx1, a.x, fma2(sy1, a.y, fma2(sz1, b.x, b.y)));
            const u64 t2 = fma2(sx2, a.x, fma2(sy2, a.y, fma2(sz2, b.x, b.y)));
            const u64 t3 = fma2(sx3, a.x, fma2(sy3, a.y, fma2(sz3, b.x, b.y)));
            float lo, hi;
            unpack2(t0, lo, hi); m0l = fminf(m0l, lo); m0h = fminf(m0h, hi);
            unpack2(t1, lo, hi); m1l = fminf(m1l, lo); m1h = fminf(m1h, hi);
            unpack2(t2, lo, hi); m2l = fminf(m2l, lo); m2h = fminf(m2h, hi);
            unpack2(t3, lo, hi); m3l = fminf(m3l, lo); m3h = fminf(m3h, hi);
        }

        tsum  = sqrtf(fmaxf(__fmaf_rn(2.0f, fminf(m0l, m0h), n0), 0.0f));
        tsum += sqrtf(fmaxf(__fmaf_rn(2.0f, fminf(m1l, m1h), n1), 0.0f));
        tsum += sqrtf(fmaxf(__fmaf_rn(2.0f, fminf(m2l, m2h), n2), 0.0f));
        tsum += sqrtf(fmaxf(__fmaf_rn(2.0f, fminf(m3l, m3h), n3), 0.0f));
    } else {
        // generic fallback (tail / other M)
        for (int p = 0; p < PPT; p++) {
            const long long i = base + p;
            if (i >= (long long)N) break;
            const float x = pts[i * 3 + 0];
            const float y = pts[i * 3 + 1];
            const float z = pts[i * 3 + 2];
            const u64 sx = pack2(-x, -x), sy = pack2(-y, -y), sz = pack2(-z, -z);
            const float nrm = __fmaf_rn(x, x, __fmaf_rn(y, y, z * z));
            float ml = 1e30f, mh = 1e30f;
            for (int k = 0; k < npair; k++) {
                const ulonglong2 a = s_xy[k];
                const ulonglong2 b = s_zc[k];
                float lo, hi;
                unpack2(fma2(sx, a.x, fma2(sy, a.y, fma2(sz, b.x, b.y))), lo, hi);
                ml = fminf(ml, lo); mh = fminf(mh, hi);
            }
            tsum += sqrtf(fmaxf(__fmaf_rn(2.0f, fminf(ml, mh), nrm), 0.0f));
        }
    }

    // ---- block reduction (deterministic order within block) ----
    #pragma unroll
    for (int o = 16; o; o >>= 1) tsum += __shfl_down_sync(0xFFFFFFFFu, tsum, o);
    if ((tid & 31) == 0) s_warp[tid >> 5] = tsum;
    __syncthreads();

    if (tid == 0) {
        float partial = 0.0f;
        #pragma unroll
        for (int w = 0; w < TPB / 32; w++) partial += s_warp[w];
        const unsigned long long q = (unsigned long long)((double)partial * SUM_SCALE);
        atomicAdd(&g_sum, q);            // return unused -> REDG (no round-trip)
        __threadfence();
        const unsigned int prev = atomicAdd(&g_count, 1u);
        s_last = (prev == gridDim.x - 1);
    }
    __syncthreads();

    if (s_last && tid == 0) {
        __threadfence();
        const unsigned long long total = atomicAdd(&g_sum, 0ULL);
        out[0] = (float)(((double)total / SUM_SCALE) / (double)N);
        g_sum = 0ULL;
        g_count = 0u;
    }
}

extern "C" void kernel_launch(void* const* d_in, const int* in_sizes, int n_in,
                              void* d_out, int out_size)
{
    const float* pts = (const float*)d_in[0];   // output_colors (N,3)
    const float* pal = (const float*)d_in[1];   // target_palette (M,3)
    float* out = (float*)d_out;

    const int N = in_sizes[0] / 3;
    int M = in_sizes[1] / 3;
    if (M > 2 * MAX_PAIRS) M = 2 * MAX_PAIRS;   // dataset has M=128

    long long blocks_ll = ((long long)N + (long long)TPB * PPT - 1) / ((long long)TPB * PPT);
    if (blocks_ll < 1) blocks_ll = 1;
    if (blocks_ll > 1048576) blocks_ll = 1048576;
    const int blocks = (int)blocks_ll;          // N=131072 -> 128 blocks

    ncd_fused<<<blocks, TPB>>>(pts, pal, out, N, M);
}

// round 10
// speedup vs baseline: 1.2694x; 1.2694x over previous
#include <cuda_runtime.h>

typedef unsigned long long u64;

// ---- packed f32x2 helpers (sm_103a) ----
__device__ __forceinline__ u64 pack2(float lo, float hi) {
    u64 r; asm("mov.b64 %0, {%1, %2};" : "=l"(r) : "f"(lo), "f"(hi)); return r;
}
__device__ __forceinline__ void unpack2(u64 v, float& lo, float& hi) {
    asm("mov.b64 {%0, %1}, %2;" : "=f"(lo), "=f"(hi) : "l"(v));  // reg rename: free
}
__device__ __forceinline__ u64 fma2(u64 a, u64 b, u64 c) {
    u64 d; asm("fma.rn.f32x2 %0, %1, %2, %3;" : "=l"(d) : "l"(a), "l"(b), "l"(c));
    return d;
}
__device__ __forceinline__ float sqrt_fast(float v) {
    float r; asm("sqrt.approx.f32 %0, %1;" : "=f"(r) : "f"(v));  // MUFU.SQRT
    return r;
}

#define TPB 256
#define PPT 4
#define MAX_PAIRS 512

// Single-atomic sum+count: bits[63:16] = fixed-point sum (scale 2^20),
// bits[15:0] = completed-block count. Integer adds commute -> deterministic,
// and sum+count update atomically together -> no fences needed.
#define SUM_SCALE 1048576.0   // 2^20
__device__ u64 g_acc = 0ULL;

// Palette as PAIRS packed in f32x2 lanes:
//   s_xy[k] = { (px_2k,px_2k+1), (py_2k,py_2k+1) }
//   s_zc[k] = { (pz_2k,pz_2k+1), (c_2k,c_2k+1) },  c = 0.5*|p|^2
// score = c - x*px - y*py - z*pz;  d = sqrt(max(|x|^2 + 2*min_score, 0))

__global__ void __launch_bounds__(TPB, 1)
ncd_fused(const float* __restrict__ pts, const float* __restrict__ pal,
          float* __restrict__ out, int N, int M)
{
    __shared__ ulonglong2 s_xy[MAX_PAIRS];
    __shared__ ulonglong2 s_zc[MAX_PAIRS];
    __shared__ float s_warp[TPB / 32];

    const int tid = threadIdx.x;
    const int npair = (M + 1) >> 1;
    const long long base = ((long long)blockIdx.x * TPB + tid) * PPT;
    const bool fast = (base + PPT <= (long long)N) && (M == 128);

    // ---- point loads FIRST: latency hides under palette build
    float x0=0.f,y0=0.f,z0=0.f,x1=0.f,y1=0.f,z1=0.f;
    float x2=0.f,y2=0.f,z2=0.f,x3=0.f,y3=0.f,z3=0.f;
    if (fast) {
        const float4* p4 = (const float4*)(pts + base * 3);
        const float4 f0 = p4[0], f1 = p4[1], f2 = p4[2];
        x0 = f0.x; y0 = f0.y; z0 = f0.z;
        x1 = f0.w; y1 = f1.x; z1 = f1.y;
        x2 = f1.z; y2 = f1.w; z2 = f2.x;
        x3 = f2.y; y3 = f2.z; z3 = f2.w;
    }

    // ---- palette build: one pair per thread (64 active for M=128)
    for (int k = tid; k < npair; k += TPB) {
        const int j0 = 2 * k;
        const int j1 = (2 * k + 1 < M) ? (2 * k + 1) : j0;
        const float px0 = pal[3 * j0 + 0], py0 = pal[3 * j0 + 1], pz0 = pal[3 * j0 + 2];
        const float px1 = pal[3 * j1 + 0], py1 = pal[3 * j1 + 1], pz1 = pal[3 * j1 + 2];
        const float c0 = 0.5f * (px0 * px0 + py0 * py0 + pz0 * pz0);
        const float c1 = 0.5f * (px1 * px1 + py1 * py1 + pz1 * pz1);
        s_xy[k] = make_ulonglong2(pack2(px0, px1), pack2(py0, py1));
        s_zc[k] = make_ulonglong2(pack2(pz0, pz1), pack2(c0, c1));
    }
    __syncthreads();

    float tsum = 0.0f;

    if (fast) {
        const u64 sx0 = pack2(-x0, -x0), sy0 = pack2(-y0, -y0), sz0 = pack2(-z0, -z0);
        const u64 sx1 = pack2(-x1, -x1), sy1 = pack2(-y1, -y1), sz1 = pack2(-z1, -z1);
        const u64 sx2 = pack2(-x2, -x2), sy2 = pack2(-y2, -y2), sz2 = pack2(-z2, -z2);
        const u64 sx3 = pack2(-x3, -x3), sy3 = pack2(-y3, -y3), sz3 = pack2(-z3, -z3);
        const float n0 = __fmaf_rn(x0, x0, __fmaf_rn(y0, y0, z0 * z0));
        const float n1 = __fmaf_rn(x1, x1, __fmaf_rn(y1, y1, z1 * z1));
        const float n2 = __fmaf_rn(x2, x2, __fmaf_rn(y2, y2, z2 * z2));
        const float n3 = __fmaf_rn(x3, x3, __fmaf_rn(y3, y3, z3 * z3));

        // init accumulators from pair 0 (no seed constants)
        float m0l, m0h, m1l, m1h, m2l, m2h, m3l, m3h;
        {
            const ulonglong2 a = s_xy[0];
            const ulonglong2 b = s_zc[0];
            unpack2(fma2(sx0, a.x, fma2(sy0, a.y, fma2(sz0, b.x, b.y))), m0l, m0h);
            unpack2(fma2(sx1, a.x, fma2(sy1, a.y, fma2(sz1, b.x, b.y))), m1l, m1h);
            unpack2(fma2(sx2, a.x, fma2(sy2, a.y, fma2(sz2, b.x, b.y))), m2l, m2h);
            unpack2(fma2(sx3, a.x, fma2(sy3, a.y, fma2(sz3, b.x, b.y))), m3l, m3h);
        }

        #pragma unroll
        for (int k = 1; k < 64; k++) {
            const ulonglong2 a = s_xy[k];
            const ulonglong2 b = s_zc[k];
            const u64 t0 = fma2(sx0, a.x, fma2(sy0, a.y, fma2(sz0, b.x, b.y)));
            const u64 t1 = fma2(sx1, a.x, fma2(sy1, a.y, fma2(sz1, b.x, b.y)));
            const u64 t2 = fma2(sx2, a.x, fma2(sy2, a.y, fma2(sz2, b.x, b.y)));
            const u64 t3 = fma2(sx3, a.x, fma2(sy3, a.y, fma2(sz3, b.x, b.y)));
            float lo, hi;
            unpack2(t0, lo, hi); m0l = fminf(m0l, lo); m0h = fminf(m0h, hi);
            unpack2(t1, lo, hi); m1l = fminf(m1l, lo); m1h = fminf(m1h, hi);
            unpack2(t2, lo, hi); m2l = fminf(m2l, lo); m2h = fminf(m2h, hi);
            unpack2(t3, lo, hi); m3l = fminf(m3l, lo); m3h = fminf(m3h, hi);
        }

        tsum  = sqrt_fast(fmaxf(__fmaf_rn(2.0f, fminf(m0l, m0h), n0), 0.0f));
        tsum += sqrt_fast(fmaxf(__fmaf_rn(2.0f, fminf(m1l, m1h), n1), 0.0f));
        tsum += sqrt_fast(fmaxf(__fmaf_rn(2.0f, fminf(m2l, m2h), n2), 0.0f));
        tsum += sqrt_fast(fmaxf(__fmaf_rn(2.0f, fminf(m3l, m3h), n3), 0.0f));
    } else {
        // generic fallback (tail / other M)
        for (int p = 0; p < PPT; p++) {
            const long long i = base + p;
            if (i >= (long long)N) break;
            const float x = pts[i * 3 + 0];
            const float y = pts[i * 3 + 1];
            const float z = pts[i * 3 + 2];
            const u64 sx = pack2(-x, -x), sy = pack2(-y, -y), sz = pack2(-z, -z);
            const float nrm = __fmaf_rn(x, x, __fmaf_rn(y, y, z * z));
            float ml = 1e30f, mh = 1e30f;
            for (int k = 0; k < npair; k++) {
                const ulonglong2 a = s_xy[k];
                const ulonglong2 b = s_zc[k];
                float lo, hi;
                unpack2(fma2(sx, a.x, fma2(sy, a.y, fma2(sz, b.x, b.y))), lo, hi);
                ml = fminf(ml, lo); mh = fminf(mh, hi);
            }
            tsum += sqrt_fast(fmaxf(__fmaf_rn(2.0f, fminf(ml, mh), nrm), 0.0f));
        }
    }

    // ---- block reduction (fixed order within block -> deterministic) ----
    #pragma unroll
    for (int o = 16; o; o >>= 1) tsum += __shfl_down_sync(0xFFFFFFFFu, tsum, o);
    if ((tid & 31) == 0) s_warp[tid >> 5] = tsum;
    __syncthreads();

    if (tid < 32) {
        float v = (tid < TPB / 32) ? s_warp[tid] : 0.0f;
        #pragma unroll
        for (int o = 4; o; o >>= 1) v += __shfl_down_sync(0xFFFFFFFFu, v, o);
        if (tid == 0) {
            // one atomic: sum (bits 63:16, fixed-point 2^20) + count (bits 15:0)
            const u64 q = (((u64)((double)v * SUM_SCALE)) << 16) | 1ULL;
            const u64 prev = atomicAdd(&g_acc, q);
            if ((prev & 0xFFFFULL) == (u64)(gridDim.x - 1)) {
                const u64 total = prev + q;
                out[0] = (float)(((double)(total >> 16) / SUM_SCALE) / (double)N);
                g_acc = 0ULL;   // reset for next graph replay
            }
        }
    }
}

extern "C" void kernel_launch(void* const* d_in, const int* in_sizes, int n_in,
                              void* d_out, int out_size)
{
    const float* pts = (const float*)d_in[0];   // output_colors (N,3)
    const float* pal = (const float*)d_in[1];   // target_palette (M,3)
    float* out = (float*)d_out;

    const int N = in_sizes[0] / 3;
    int M = in_sizes[1] / 3;
    if (M > 2 * MAX_PAIRS) M = 2 * MAX_PAIRS;   // dataset has M=128

    long long blocks_ll = ((long long)N + (long long)TPB * PPT - 1) / ((long long)TPB * PPT);
    if (blocks_ll < 1) blocks_ll = 1;
    if (blocks_ll > 65535) blocks_ll = 65535;   // count field is 16 bits
    const int blocks = (int)blocks_ll;          // N=131072 -> 128 blocks

    ncd_fused<<<blocks, TPB>>>(pts, pal, out, N, M);
}